// round 1
// baseline (speedup 1.0000x reference)
#include <cuda_runtime.h>
#include <math.h>

#define BATCH 2
#define SEQ   2048
#define DMODEL 1024
#define NHEAD 16
#define HDIM  64
#define MTOT  (BATCH * SEQ)   // 4096

// Scratch (allocation-free rule: __device__ globals)
__device__ float g_q[(size_t)MTOT * DMODEL];        // 16 MB
__device__ float g_kv[(size_t)MTOT * 2 * DMODEL];   // 32 MB
__device__ float g_y[(size_t)MTOT * DMODEL];        // 16 MB

// ---------------------------------------------------------------------------
// C[M,N] = A[M,K] @ W[N,K]^T + bias[N]   (torch Linear, both K-contiguous)
// 128x128 tile, BK=8, 256 threads, 8x8 register tile per thread.
// ---------------------------------------------------------------------------
__global__ __launch_bounds__(256) void sgemm_nt_bias(
    const float* __restrict__ A, const float* __restrict__ W,
    const float* __restrict__ bias, float* __restrict__ C,
    int M, int N, int K)
{
    const int BK = 8;
    __shared__ float As[BK][128];
    __shared__ float Ws[BK][128];

    int tid = threadIdx.x;
    int tx = tid & 15;        // 0..15
    int ty = tid >> 4;        // 0..15
    int bm = blockIdx.y * 128;
    int bn = blockIdx.x * 128;

    int lr = tid >> 1;            // 0..127
    int lc = (tid & 1) * 4;       // 0 or 4
    const float* Ap = A + (size_t)(bm + lr) * K + lc;
    const float* Wp = W + (size_t)(bn + lr) * K + lc;

    float acc[8][8];
#pragma unroll
    for (int i = 0; i < 8; i++)
#pragma unroll
        for (int j = 0; j < 8; j++) acc[i][j] = 0.0f;

    for (int k0 = 0; k0 < K; k0 += BK) {
        float4 a = *(const float4*)(Ap + k0);
        float4 w = *(const float4*)(Wp + k0);
        As[lc + 0][lr] = a.x; As[lc + 1][lr] = a.y;
        As[lc + 2][lr] = a.z; As[lc + 3][lr] = a.w;
        Ws[lc + 0][lr] = w.x; Ws[lc + 1][lr] = w.y;
        Ws[lc + 2][lr] = w.z; Ws[lc + 3][lr] = w.w;
        __syncthreads();

#pragma unroll
        for (int kk = 0; kk < BK; kk++) {
            float4 a0 = *(const float4*)&As[kk][ty * 8];
            float4 a1 = *(const float4*)&As[kk][ty * 8 + 4];
            float4 w0 = *(const float4*)&Ws[kk][tx * 8];
            float4 w1 = *(const float4*)&Ws[kk][tx * 8 + 4];
            float ra[8] = {a0.x, a0.y, a0.z, a0.w, a1.x, a1.y, a1.z, a1.w};
            float rw[8] = {w0.x, w0.y, w0.z, w0.w, w1.x, w1.y, w1.z, w1.w};
#pragma unroll
            for (int i = 0; i < 8; i++)
#pragma unroll
                for (int j = 0; j < 8; j++)
                    acc[i][j] = fmaf(ra[i], rw[j], acc[i][j]);
        }
        __syncthreads();
    }

#pragma unroll
    for (int i = 0; i < 8; i++) {
        int row = bm + ty * 8 + i;
#pragma unroll
        for (int j = 0; j < 8; j++) {
            int col = bn + tx * 8 + j;
            C[(size_t)row * N + col] = acc[i][j] + bias[col];
        }
    }
}

// ---------------------------------------------------------------------------
// Flash-style causal attention with ALiBi, fp32.
// Block = (b, h, 64-query tile). 256 threads (16x16), 4x4 register tiles.
// Online softmax; P routed through smem for the O-gemm.
// ---------------------------------------------------------------------------
__global__ __launch_bounds__(256) void attn_kernel(
    const float* __restrict__ q, const float* __restrict__ kv,
    float* __restrict__ y)
{
    extern __shared__ float sm[];
    // Qs, Ks: [d][m] transposed, rows padded to 65 (bank-conflict mitigation)
    float (*Qs)[65] = (float (*)[65])(sm);
    float (*Ks)[65] = (float (*)[65])(sm + 64 * 65);
    float (*Ps)[65] = (float (*)[65])(sm + 2 * 64 * 65);   // [key][query]
    float (*Vs)[64] = (float (*)[64])(sm + 3 * 64 * 65);   // [key][d]

    int tid = threadIdx.x;
    int tx = tid & 15;       // 0..15 -> key cols / dh cols
    int ty = tid >> 4;       // 0..15 -> query rows
    int qt = blockIdx.x;
    int h  = blockIdx.y;
    int b  = blockIdx.z;
    int q0 = qt * 64;
    float slope = (float)(h + 1) / (float)NHEAD;

    // loader mapping: 64x64 tile, 256 threads, 4x float4 each
    int lrow = tid >> 2;            // 0..63
    int lcol = (tid & 3) * 16;      // 0,16,32,48

    // ---- load Q tile (transposed into Qs) ----
    {
        const float* src = q + ((size_t)(b * SEQ + q0 + lrow)) * DMODEL + h * HDIM;
#pragma unroll
        for (int u = 0; u < 4; u++) {
            float4 v = *(const float4*)(src + lcol + 4 * u);
            Qs[lcol + 4 * u + 0][lrow] = v.x;
            Qs[lcol + 4 * u + 1][lrow] = v.y;
            Qs[lcol + 4 * u + 2][lrow] = v.z;
            Qs[lcol + 4 * u + 3][lrow] = v.w;
        }
    }

    float m_i[4], l_i[4], acc[4][4];
#pragma unroll
    for (int i = 0; i < 4; i++) {
        m_i[i] = -1e30f; l_i[i] = 0.0f;
#pragma unroll
        for (int j = 0; j < 4; j++) acc[i][j] = 0.0f;
    }

    for (int kt = 0; kt <= qt; kt++) {
        int k0 = kt * 64;
        __syncthreads();  // previous O-gemm done (and orders Q stores on iter 0)

        // ---- load K (transposed into Ks) and V (natural into Vs) ----
        {
            const float* ksrc = kv + ((size_t)(b * SEQ + k0 + lrow)) * (2 * DMODEL) + h * HDIM;
            const float* vsrc = ksrc + DMODEL;
#pragma unroll
            for (int u = 0; u < 4; u++) {
                float4 kvv = *(const float4*)(ksrc + lcol + 4 * u);
                Ks[lcol + 4 * u + 0][lrow] = kvv.x;
                Ks[lcol + 4 * u + 1][lrow] = kvv.y;
                Ks[lcol + 4 * u + 2][lrow] = kvv.z;
                Ks[lcol + 4 * u + 3][lrow] = kvv.w;
                float4 vv = *(const float4*)(vsrc + lcol + 4 * u);
                *(float4*)&Vs[lrow][lcol + 4 * u] = vv;
            }
        }
        __syncthreads();

        // ---- S = Q @ K^T (4x4 per thread) ----
        float s[4][4];
#pragma unroll
        for (int i = 0; i < 4; i++)
#pragma unroll
            for (int j = 0; j < 4; j++) s[i][j] = 0.0f;

#pragma unroll 8
        for (int kk = 0; kk < 64; kk++) {
            float qa[4], kb[4];
#pragma unroll
            for (int i = 0; i < 4; i++) qa[i] = Qs[kk][ty * 4 + i];
#pragma unroll
            for (int j = 0; j < 4; j++) kb[j] = Ks[kk][tx * 4 + j];
#pragma unroll
            for (int i = 0; i < 4; i++)
#pragma unroll
                for (int j = 0; j < 4; j++)
                    s[i][j] = fmaf(qa[i], kb[j], s[i][j]);
        }

        // ---- scale + ALiBi + causal mask ----
        bool diag = (kt == qt);
#pragma unroll
        for (int i = 0; i < 4; i++) {
            int qrow = q0 + ty * 4 + i;
#pragma unroll
            for (int j = 0; j < 4; j++) {
                int kcol = k0 + tx * 4 + j;
                float v = s[i][j] * 0.125f + slope * (float)(kcol - qrow);
                s[i][j] = (!diag || kcol <= qrow) ? v : -1e30f;
            }
        }

        // ---- online softmax update ----
#pragma unroll
        for (int i = 0; i < 4; i++) {
            float rm = s[i][0];
#pragma unroll
            for (int j = 1; j < 4; j++) rm = fmaxf(rm, s[i][j]);
#pragma unroll
            for (int off = 8; off > 0; off >>= 1)
                rm = fmaxf(rm, __shfl_xor_sync(0xffffffffu, rm, off));
            float mnew = fmaxf(m_i[i], rm);
            float scale = __expf(m_i[i] - mnew);
            m_i[i] = mnew;
            float rs = 0.0f;
#pragma unroll
            for (int j = 0; j < 4; j++) {
                float p = __expf(s[i][j] - mnew);
                s[i][j] = p;
                rs += p;
            }
#pragma unroll
            for (int off = 8; off > 0; off >>= 1)
                rs += __shfl_xor_sync(0xffffffffu, rs, off);
            l_i[i] = l_i[i] * scale + rs;
#pragma unroll
            for (int j = 0; j < 4; j++) acc[i][j] *= scale;
        }

        // ---- store P^T to smem ----
#pragma unroll
        for (int i = 0; i < 4; i++)
#pragma unroll
            for (int j = 0; j < 4; j++)
                Ps[tx * 4 + j][ty * 4 + i] = s[i][j];
        __syncthreads();

        // ---- O += P @ V ----
#pragma unroll 8
        for (int kk = 0; kk < 64; kk++) {
            float pa[4], vb[4];
#pragma unroll
            for (int i = 0; i < 4; i++) pa[i] = Ps[kk][ty * 4 + i];
#pragma unroll
            for (int j = 0; j < 4; j++) vb[j] = Vs[kk][tx * 4 + j];
#pragma unroll
            for (int i = 0; i < 4; i++)
#pragma unroll
                for (int j = 0; j < 4; j++)
                    acc[i][j] = fmaf(pa[i], vb[j], acc[i][j]);
        }
    }

    // ---- epilogue: normalize and write y[b][row][h*HDIM + col] ----
#pragma unroll
    for (int i = 0; i < 4; i++) {
        float inv = 1.0f / l_i[i];
        int row = q0 + ty * 4 + i;
        float* dst = y + ((size_t)(b * SEQ + row)) * DMODEL + h * HDIM + tx * 4;
        float4 o;
        o.x = acc[i][0] * inv; o.y = acc[i][1] * inv;
        o.z = acc[i][2] * inv; o.w = acc[i][3] * inv;
        *(float4*)dst = o;
    }
}

// ---------------------------------------------------------------------------
extern "C" void kernel_launch(void* const* d_in, const int* in_sizes, int n_in,
                              void* d_out, int out_size)
{
    const float* x   = (const float*)d_in[0];
    // d_in[1] = freqs_cis (unused under ALiBi)
    const float* Wq  = (const float*)d_in[2];
    const float* bq  = (const float*)d_in[3];
    const float* Wkv = (const float*)d_in[4];
    const float* bkv = (const float*)d_in[5];
    const float* Wo  = (const float*)d_in[6];
    const float* bo  = (const float*)d_in[7];
    float* out = (float*)d_out;

    void *pq, *pkv, *py;
    cudaGetSymbolAddress(&pq, g_q);
    cudaGetSymbolAddress(&pkv, g_kv);
    cudaGetSymbolAddress(&py, g_y);
    float* qb  = (float*)pq;
    float* kvb = (float*)pkv;
    float* yb  = (float*)py;

    // Q projection: [4096,1024] = x @ Wq^T + bq
    sgemm_nt_bias<<<dim3(DMODEL / 128, MTOT / 128), 256>>>(
        x, Wq, bq, qb, MTOT, DMODEL, DMODEL);

    // KV projection: [4096,2048] = x @ Wkv^T + bkv
    sgemm_nt_bias<<<dim3(2 * DMODEL / 128, MTOT / 128), 256>>>(
        x, Wkv, bkv, kvb, MTOT, 2 * DMODEL, DMODEL);

    // Attention
    size_t shmem = (size_t)(3 * 64 * 65 + 64 * 64) * sizeof(float);  // 66304 B
    static bool attr_set = false;
    cudaFuncSetAttribute(attn_kernel, cudaFuncAttributeMaxDynamicSharedMemorySize,
                         (int)shmem);
    (void)attr_set;
    attn_kernel<<<dim3(SEQ / 64, NHEAD, BATCH), 256, shmem>>>(qb, kvb, yb);

    // Output projection: out = y @ Wo^T + bo
    sgemm_nt_bias<<<dim3(DMODEL / 128, MTOT / 128), 256>>>(
        yb, Wo, bo, out, MTOT, DMODEL, DMODEL);
}

// round 3
// speedup vs baseline: 1.4494x; 1.4494x over previous
#include <cuda_runtime.h>
#include <cstdint>
#include <math.h>

#define BATCH 2
#define SEQ   2048
#define DMODEL 1024
#define NHEAD 16
#define HDIM  64
#define MTOT  (BATCH * SEQ)   // 4096

// Scratch (allocation-free rule: __device__ globals)
__device__ float g_q[(size_t)MTOT * DMODEL];        // 16 MB
__device__ float g_kv[(size_t)MTOT * 2 * DMODEL];   // 32 MB
__device__ float g_y[(size_t)MTOT * DMODEL];        // 16 MB

// ---------------------------------------------------------------------------
// mma.sync tf32 helper (sm_80+ ISA -> compiles for compute_103)
// D = A(16x8, row) * B(8x8, col) + D, fp32 accum
// ---------------------------------------------------------------------------
__device__ __forceinline__ void mma_tf32(float* c, const uint32_t* a,
                                         const uint32_t* b) {
    asm volatile(
        "mma.sync.aligned.m16n8k8.row.col.f32.tf32.tf32.f32 "
        "{%0,%1,%2,%3}, {%4,%5,%6,%7}, {%8,%9}, {%0,%1,%2,%3};"
        : "+f"(c[0]), "+f"(c[1]), "+f"(c[2]), "+f"(c[3])
        : "r"(a[0]), "r"(a[1]), "r"(a[2]), "r"(a[3]),
          "r"(b[0]), "r"(b[1]));
}

__device__ __forceinline__ uint32_t f2tf32(float f) {
    uint32_t r;
    asm("cvt.rna.tf32.f32 %0, %1;" : "=r"(r) : "f"(f));
    return r;
}

// ---------------------------------------------------------------------------
// tf32 tensor-core GEMM: C[M,N] = A[M,K] @ W[N,K]^T + bias[N]
// 128x128 CTA tile, BK=32, 256 threads (8 warps, 4x2), warp tile 32x64.
// Double-buffered smem, padded rows (stride 36) -> conflict-free frag loads.
// ---------------------------------------------------------------------------
#define GSTRIDE 36
#define GBUF (128 * GSTRIDE)          // u32 per operand per buffer

__global__ __launch_bounds__(256) void mma_gemm_nt_bias(
    const float* __restrict__ A, const float* __restrict__ W,
    const float* __restrict__ bias, float* __restrict__ C,
    int N, int K)
{
    extern __shared__ uint32_t sh[];
    // layout: [buf][A(128*36) | W(128*36)]
    const int tid = threadIdx.x;
    const int wid = tid >> 5;
    const int lane = tid & 31;
    const int grp = lane >> 2;          // 0..7
    const int qid = lane & 3;           // 0..3

    const int bm = blockIdx.y * 128;
    const int bn = blockIdx.x * 128;

    const int rbase = (wid & 3) * 32;   // warp M offset in tile
    const int nbase = (wid >> 2) * 64;  // warp N offset in tile

    // loader mapping: row = tid>>1 (0..127), kbase = (tid&1)*16
    const int lrow = tid >> 1;
    const int kbase = (tid & 1) * 16;
    const float* Ap = A + (size_t)(bm + lrow) * K + kbase;
    const float* Wp = W + (size_t)(bn + lrow) * K + kbase;
    const int soff = lrow * GSTRIDE + kbase;

    float acc[2][8][4];
#pragma unroll
    for (int mi = 0; mi < 2; mi++)
#pragma unroll
        for (int ni = 0; ni < 8; ni++)
#pragma unroll
            for (int v = 0; v < 4; v++) acc[mi][ni][v] = 0.0f;

    const int NC = K / 32;

    // ---- preload chunk 0 ----
    float4 ra[2], rw[2];
#pragma unroll
    for (int u = 0; u < 2; u++) {
        ra[u] = *(const float4*)(Ap + 8 * u);
        ra[u].x = __uint_as_float(f2tf32(ra[u].x));
        ra[u].y = __uint_as_float(f2tf32(ra[u].y));
        ra[u].z = __uint_as_float(f2tf32(ra[u].z));
        ra[u].w = __uint_as_float(f2tf32(ra[u].w));
        float4 t = *(const float4*)(Ap + 8 * u + 4);
        rw[u] = t;  // temp reuse below; store both halves
        // store A half u
        *(float4*)&sh[soff + 8 * u] = ra[u];
        float4 t2;
        t2.x = __uint_as_float(f2tf32(t.x));
        t2.y = __uint_as_float(f2tf32(t.y));
        t2.z = __uint_as_float(f2tf32(t.z));
        t2.w = __uint_as_float(f2tf32(t.w));
        *(float4*)&sh[soff + 8 * u + 4] = t2;
    }
#pragma unroll
    for (int u = 0; u < 4; u++) {
        float4 t = *(const float4*)(Wp + 4 * u);
        float4 t2;
        t2.x = __uint_as_float(f2tf32(t.x));
        t2.y = __uint_as_float(f2tf32(t.y));
        t2.z = __uint_as_float(f2tf32(t.z));
        t2.w = __uint_as_float(f2tf32(t.w));
        *(float4*)&sh[GBUF + soff + 4 * u] = t2;
    }
    __syncthreads();

    float4 pf[8];   // prefetch regs (4 A + 4 W float4)

    for (int c = 0; c < NC; c++) {
        const uint32_t* Ab = sh + (c & 1) * (2 * GBUF);
        const uint32_t* Wb = Ab + GBUF;

        // prefetch next chunk from gmem
        if (c + 1 < NC) {
            const int k0 = (c + 1) * 32;
#pragma unroll
            for (int u = 0; u < 4; u++) pf[u] = *(const float4*)(Ap + k0 + 4 * u);
#pragma unroll
            for (int u = 0; u < 4; u++) pf[4 + u] = *(const float4*)(Wp + k0 + 4 * u);
        }

        // compute on current buffer
#pragma unroll
        for (int ks = 0; ks < 4; ks++) {
            uint32_t afr[2][4];
#pragma unroll
            for (int mi = 0; mi < 2; mi++) {
                const int r0 = rbase + mi * 16 + grp;
                const int col = ks * 8 + qid;
                afr[mi][0] = Ab[r0 * GSTRIDE + col];
                afr[mi][1] = Ab[(r0 + 8) * GSTRIDE + col];
                afr[mi][2] = Ab[r0 * GSTRIDE + col + 4];
                afr[mi][3] = Ab[(r0 + 8) * GSTRIDE + col + 4];
            }
            uint32_t bfr[8][2];
#pragma unroll
            for (int ni = 0; ni < 8; ni++) {
                const int nrow = nbase + ni * 8 + grp;
                bfr[ni][0] = Wb[nrow * GSTRIDE + ks * 8 + qid];
                bfr[ni][1] = Wb[nrow * GSTRIDE + ks * 8 + qid + 4];
            }
#pragma unroll
            for (int mi = 0; mi < 2; mi++)
#pragma unroll
                for (int ni = 0; ni < 8; ni++)
                    mma_tf32(acc[mi][ni], afr[mi], bfr[ni]);
        }

        // store prefetched chunk to other buffer
        if (c + 1 < NC) {
            uint32_t* Ab2 = sh + ((c + 1) & 1) * (2 * GBUF);
            uint32_t* Wb2 = Ab2 + GBUF;
#pragma unroll
            for (int u = 0; u < 4; u++) {
                float4 t = pf[u];
                float4 t2;
                t2.x = __uint_as_float(f2tf32(t.x));
                t2.y = __uint_as_float(f2tf32(t.y));
                t2.z = __uint_as_float(f2tf32(t.z));
                t2.w = __uint_as_float(f2tf32(t.w));
                *(float4*)&Ab2[soff + 4 * u] = t2;
            }
#pragma unroll
            for (int u = 0; u < 4; u++) {
                float4 t = pf[4 + u];
                float4 t2;
                t2.x = __uint_as_float(f2tf32(t.x));
                t2.y = __uint_as_float(f2tf32(t.y));
                t2.z = __uint_as_float(f2tf32(t.z));
                t2.w = __uint_as_float(f2tf32(t.w));
                *(float4*)&Wb2[soff + 4 * u] = t2;
            }
        }
        __syncthreads();
    }

    // ---- epilogue ----
#pragma unroll
    for (int mi = 0; mi < 2; mi++) {
        const int row = bm + rbase + mi * 16 + grp;
#pragma unroll
        for (int ni = 0; ni < 8; ni++) {
            const int col = bn + nbase + ni * 8 + 2 * qid;
            const float2 bv = *(const float2*)(bias + col);
            float2 o0, o1;
            o0.x = acc[mi][ni][0] + bv.x;
            o0.y = acc[mi][ni][1] + bv.y;
            o1.x = acc[mi][ni][2] + bv.x;
            o1.y = acc[mi][ni][3] + bv.y;
            *(float2*)(C + (size_t)row * N + col) = o0;
            *(float2*)(C + (size_t)(row + 8) * N + col) = o1;
        }
    }
}

// ---------------------------------------------------------------------------
// Flash-style causal attention with ALiBi, fp32 (unchanged, validated R1).
// ---------------------------------------------------------------------------
__global__ __launch_bounds__(256) void attn_kernel(
    const float* __restrict__ q, const float* __restrict__ kv,
    float* __restrict__ y)
{
    extern __shared__ float sm[];
    float (*Qs)[65] = (float (*)[65])(sm);
    float (*Ks)[65] = (float (*)[65])(sm + 64 * 65);
    float (*Ps)[65] = (float (*)[65])(sm + 2 * 64 * 65);
    float (*Vs)[64] = (float (*)[64])(sm + 3 * 64 * 65);

    int tid = threadIdx.x;
    int tx = tid & 15;
    int ty = tid >> 4;
    int qt = blockIdx.x;
    int h  = blockIdx.y;
    int b  = blockIdx.z;
    int q0 = qt * 64;
    float slope = (float)(h + 1) / (float)NHEAD;

    int lrow = tid >> 2;
    int lcol = (tid & 3) * 16;

    {
        const float* src = q + ((size_t)(b * SEQ + q0 + lrow)) * DMODEL + h * HDIM;
#pragma unroll
        for (int u = 0; u < 4; u++) {
            float4 v = *(const float4*)(src + lcol + 4 * u);
            Qs[lcol + 4 * u + 0][lrow] = v.x;
            Qs[lcol + 4 * u + 1][lrow] = v.y;
            Qs[lcol + 4 * u + 2][lrow] = v.z;
            Qs[lcol + 4 * u + 3][lrow] = v.w;
        }
    }

    float m_i[4], l_i[4], acc[4][4];
#pragma unroll
    for (int i = 0; i < 4; i++) {
        m_i[i] = -1e30f; l_i[i] = 0.0f;
#pragma unroll
        for (int j = 0; j < 4; j++) acc[i][j] = 0.0f;
    }

    for (int kt = 0; kt <= qt; kt++) {
        int k0 = kt * 64;
        __syncthreads();

        {
            const float* ksrc = kv + ((size_t)(b * SEQ + k0 + lrow)) * (2 * DMODEL) + h * HDIM;
            const float* vsrc = ksrc + DMODEL;
#pragma unroll
            for (int u = 0; u < 4; u++) {
                float4 kvv = *(const float4*)(ksrc + lcol + 4 * u);
                Ks[lcol + 4 * u + 0][lrow] = kvv.x;
                Ks[lcol + 4 * u + 1][lrow] = kvv.y;
                Ks[lcol + 4 * u + 2][lrow] = kvv.z;
                Ks[lcol + 4 * u + 3][lrow] = kvv.w;
                float4 vv = *(const float4*)(vsrc + lcol + 4 * u);
                *(float4*)&Vs[lrow][lcol + 4 * u] = vv;
            }
        }
        __syncthreads();

        float s[4][4];
#pragma unroll
        for (int i = 0; i < 4; i++)
#pragma unroll
            for (int j = 0; j < 4; j++) s[i][j] = 0.0f;

#pragma unroll 8
        for (int kk = 0; kk < 64; kk++) {
            float qa[4], kb[4];
#pragma unroll
            for (int i = 0; i < 4; i++) qa[i] = Qs[kk][ty * 4 + i];
#pragma unroll
            for (int j = 0; j < 4; j++) kb[j] = Ks[kk][tx * 4 + j];
#pragma unroll
            for (int i = 0; i < 4; i++)
#pragma unroll
                for (int j = 0; j < 4; j++)
                    s[i][j] = fmaf(qa[i], kb[j], s[i][j]);
        }

        bool diag = (kt == qt);
#pragma unroll
        for (int i = 0; i < 4; i++) {
            int qrow = q0 + ty * 4 + i;
#pragma unroll
            for (int j = 0; j < 4; j++) {
                int kcol = k0 + tx * 4 + j;
                float v = s[i][j] * 0.125f + slope * (float)(kcol - qrow);
                s[i][j] = (!diag || kcol <= qrow) ? v : -1e30f;
            }
        }

#pragma unroll
        for (int i = 0; i < 4; i++) {
            float rm = s[i][0];
#pragma unroll
            for (int j = 1; j < 4; j++) rm = fmaxf(rm, s[i][j]);
#pragma unroll
            for (int off = 8; off > 0; off >>= 1)
                rm = fmaxf(rm, __shfl_xor_sync(0xffffffffu, rm, off));
            float mnew = fmaxf(m_i[i], rm);
            float scale = __expf(m_i[i] - mnew);
            m_i[i] = mnew;
            float rs = 0.0f;
#pragma unroll
            for (int j = 0; j < 4; j++) {
                float p = __expf(s[i][j] - mnew);
                s[i][j] = p;
                rs += p;
            }
#pragma unroll
            for (int off = 8; off > 0; off >>= 1)
                rs += __shfl_xor_sync(0xffffffffu, rs, off);
            l_i[i] = l_i[i] * scale + rs;
#pragma unroll
            for (int j = 0; j < 4; j++) acc[i][j] *= scale;
        }

#pragma unroll
        for (int i = 0; i < 4; i++)
#pragma unroll
            for (int j = 0; j < 4; j++)
                Ps[tx * 4 + j][ty * 4 + i] = s[i][j];
        __syncthreads();

#pragma unroll 8
        for (int kk = 0; kk < 64; kk++) {
            float pa[4], vb[4];
#pragma unroll
            for (int i = 0; i < 4; i++) pa[i] = Ps[kk][ty * 4 + i];
#pragma unroll
            for (int j = 0; j < 4; j++) vb[j] = Vs[kk][tx * 4 + j];
#pragma unroll
            for (int i = 0; i < 4; i++)
#pragma unroll
                for (int j = 0; j < 4; j++)
                    acc[i][j] = fmaf(pa[i], vb[j], acc[i][j]);
        }
    }

#pragma unroll
    for (int i = 0; i < 4; i++) {
        float inv = 1.0f / l_i[i];
        int row = q0 + ty * 4 + i;
        float* dst = y + ((size_t)(b * SEQ + row)) * DMODEL + h * HDIM + tx * 4;
        float4 o;
        o.x = acc[i][0] * inv; o.y = acc[i][1] * inv;
        o.z = acc[i][2] * inv; o.w = acc[i][3] * inv;
        *(float4*)dst = o;
    }
}

// ---------------------------------------------------------------------------
extern "C" void kernel_launch(void* const* d_in, const int* in_sizes, int n_in,
                              void* d_out, int out_size)
{
    const float* x   = (const float*)d_in[0];
    const float* Wq  = (const float*)d_in[2];
    const float* bq  = (const float*)d_in[3];
    const float* Wkv = (const float*)d_in[4];
    const float* bkv = (const float*)d_in[5];
    const float* Wo  = (const float*)d_in[6];
    const float* bo  = (const float*)d_in[7];
    float* out = (float*)d_out;

    void *pq, *pkv, *py;
    cudaGetSymbolAddress(&pq, g_q);
    cudaGetSymbolAddress(&pkv, g_kv);
    cudaGetSymbolAddress(&py, g_y);
    float* qb  = (float*)pq;
    float* kvb = (float*)pkv;
    float* yb  = (float*)py;

    const int gemm_smem = 2 * 2 * GBUF * 4;   // 73728 B
    cudaFuncSetAttribute(mma_gemm_nt_bias,
                         cudaFuncAttributeMaxDynamicSharedMemorySize, gemm_smem);

    // Q projection: [4096,1024] = x @ Wq^T + bq
    mma_gemm_nt_bias<<<dim3(DMODEL / 128, MTOT / 128), 256, gemm_smem>>>(
        x, Wq, bq, qb, DMODEL, DMODEL);

    // KV projection: [4096,2048] = x @ Wkv^T + bkv
    mma_gemm_nt_bias<<<dim3(2 * DMODEL / 128, MTOT / 128), 256, gemm_smem>>>(
        x, Wkv, bkv, kvb, 2 * DMODEL, DMODEL);

    // Attention
    size_t shmem = (size_t)(3 * 64 * 65 + 64 * 64) * sizeof(float);
    cudaFuncSetAttribute(attn_kernel, cudaFuncAttributeMaxDynamicSharedMemorySize,
                         (int)shmem);
    attn_kernel<<<dim3(SEQ / 64, NHEAD, BATCH), 256, shmem>>>(qb, kvb, yb);

    // Output projection: out = y @ Wo^T + bo
    mma_gemm_nt_bias<<<dim3(DMODEL / 128, MTOT / 128), 256, gemm_smem>>>(
        yb, Wo, bo, out, DMODEL, DMODEL);
}

// round 4
// speedup vs baseline: 2.5136x; 1.7342x over previous
#include <cuda_runtime.h>
#include <cstdint>
#include <math.h>

#define BATCH 2
#define SEQ   2048
#define DMODEL 1024
#define NHEAD 16
#define HDIM  64
#define MTOT  (BATCH * SEQ)   // 4096

// Scratch (allocation-free rule: __device__ globals)
__device__ float g_q[(size_t)MTOT * DMODEL];        // 16 MB
__device__ float g_kv[(size_t)MTOT * 2 * DMODEL];   // 32 MB
__device__ float g_y[(size_t)MTOT * DMODEL];        // 16 MB

// ---------------------------------------------------------------------------
// mma.sync tf32: D(16x8) += A(16x8 row) * B(8x8 col), fp32 accum
// ---------------------------------------------------------------------------
__device__ __forceinline__ void mma_tf32(float* c, const uint32_t* a,
                                         const uint32_t* b) {
    asm volatile(
        "mma.sync.aligned.m16n8k8.row.col.f32.tf32.tf32.f32 "
        "{%0,%1,%2,%3}, {%4,%5,%6,%7}, {%8,%9}, {%0,%1,%2,%3};"
        : "+f"(c[0]), "+f"(c[1]), "+f"(c[2]), "+f"(c[3])
        : "r"(a[0]), "r"(a[1]), "r"(a[2]), "r"(a[3]),
          "r"(b[0]), "r"(b[1]));
}

__device__ __forceinline__ uint32_t f2tf32(float f) {
    uint32_t r;
    asm("cvt.rna.tf32.f32 %0, %1;" : "=r"(r) : "f"(f));
    return r;
}

// ---------------------------------------------------------------------------
// tf32 tensor-core GEMM: C[M,N] = A[M,K] @ W[N,K]^T + bias[N]  (unchanged R3)
// ---------------------------------------------------------------------------
#define GSTRIDE 36
#define GBUF (128 * GSTRIDE)

__global__ __launch_bounds__(256) void mma_gemm_nt_bias(
    const float* __restrict__ A, const float* __restrict__ W,
    const float* __restrict__ bias, float* __restrict__ C,
    int N, int K)
{
    extern __shared__ uint32_t sh[];
    const int tid = threadIdx.x;
    const int wid = tid >> 5;
    const int lane = tid & 31;
    const int grp = lane >> 2;
    const int qid = lane & 3;

    const int bm = blockIdx.y * 128;
    const int bn = blockIdx.x * 128;
    const int rbase = (wid & 3) * 32;
    const int nbase = (wid >> 2) * 64;

    const int lrow = tid >> 1;
    const int kbase = (tid & 1) * 16;
    const float* Ap = A + (size_t)(bm + lrow) * K + kbase;
    const float* Wp = W + (size_t)(bn + lrow) * K + kbase;
    const int soff = lrow * GSTRIDE + kbase;

    float acc[2][8][4];
#pragma unroll
    for (int mi = 0; mi < 2; mi++)
#pragma unroll
        for (int ni = 0; ni < 8; ni++)
#pragma unroll
            for (int v = 0; v < 4; v++) acc[mi][ni][v] = 0.0f;

    const int NC = K / 32;

#pragma unroll
    for (int u = 0; u < 4; u++) {
        float4 t = *(const float4*)(Ap + 4 * u);
        float4 t2;
        t2.x = __uint_as_float(f2tf32(t.x));
        t2.y = __uint_as_float(f2tf32(t.y));
        t2.z = __uint_as_float(f2tf32(t.z));
        t2.w = __uint_as_float(f2tf32(t.w));
        *(float4*)&sh[soff + 4 * u] = t2;
    }
#pragma unroll
    for (int u = 0; u < 4; u++) {
        float4 t = *(const float4*)(Wp + 4 * u);
        float4 t2;
        t2.x = __uint_as_float(f2tf32(t.x));
        t2.y = __uint_as_float(f2tf32(t.y));
        t2.z = __uint_as_float(f2tf32(t.z));
        t2.w = __uint_as_float(f2tf32(t.w));
        *(float4*)&sh[GBUF + soff + 4 * u] = t2;
    }
    __syncthreads();

    float4 pf[8];

    for (int c = 0; c < NC; c++) {
        const uint32_t* Ab = sh + (c & 1) * (2 * GBUF);
        const uint32_t* Wb = Ab + GBUF;

        if (c + 1 < NC) {
            const int k0 = (c + 1) * 32;
#pragma unroll
            for (int u = 0; u < 4; u++) pf[u] = *(const float4*)(Ap + k0 + 4 * u);
#pragma unroll
            for (int u = 0; u < 4; u++) pf[4 + u] = *(const float4*)(Wp + k0 + 4 * u);
        }

#pragma unroll
        for (int ks = 0; ks < 4; ks++) {
            uint32_t afr[2][4];
#pragma unroll
            for (int mi = 0; mi < 2; mi++) {
                const int r0 = rbase + mi * 16 + grp;
                const int col = ks * 8 + qid;
                afr[mi][0] = Ab[r0 * GSTRIDE + col];
                afr[mi][1] = Ab[(r0 + 8) * GSTRIDE + col];
                afr[mi][2] = Ab[r0 * GSTRIDE + col + 4];
                afr[mi][3] = Ab[(r0 + 8) * GSTRIDE + col + 4];
            }
            uint32_t bfr[8][2];
#pragma unroll
            for (int ni = 0; ni < 8; ni++) {
                const int nrow = nbase + ni * 8 + grp;
                bfr[ni][0] = Wb[nrow * GSTRIDE + ks * 8 + qid];
                bfr[ni][1] = Wb[nrow * GSTRIDE + ks * 8 + qid + 4];
            }
#pragma unroll
            for (int mi = 0; mi < 2; mi++)
#pragma unroll
                for (int ni = 0; ni < 8; ni++)
                    mma_tf32(acc[mi][ni], afr[mi], bfr[ni]);
        }

        if (c + 1 < NC) {
            uint32_t* Ab2 = sh + ((c + 1) & 1) * (2 * GBUF);
            uint32_t* Wb2 = Ab2 + GBUF;
#pragma unroll
            for (int u = 0; u < 4; u++) {
                float4 t = pf[u];
                float4 t2;
                t2.x = __uint_as_float(f2tf32(t.x));
                t2.y = __uint_as_float(f2tf32(t.y));
                t2.z = __uint_as_float(f2tf32(t.z));
                t2.w = __uint_as_float(f2tf32(t.w));
                *(float4*)&Ab2[soff + 4 * u] = t2;
            }
#pragma unroll
            for (int u = 0; u < 4; u++) {
                float4 t = pf[4 + u];
                float4 t2;
                t2.x = __uint_as_float(f2tf32(t.x));
                t2.y = __uint_as_float(f2tf32(t.y));
                t2.z = __uint_as_float(f2tf32(t.z));
                t2.w = __uint_as_float(f2tf32(t.w));
                *(float4*)&Wb2[soff + 4 * u] = t2;
            }
        }
        __syncthreads();
    }

#pragma unroll
    for (int mi = 0; mi < 2; mi++) {
        const int row = bm + rbase + mi * 16 + grp;
#pragma unroll
        for (int ni = 0; ni < 8; ni++) {
            const int col = bn + nbase + ni * 8 + 2 * qid;
            const float2 bv = *(const float2*)(bias + col);
            float2 o0, o1;
            o0.x = acc[mi][ni][0] + bv.x;
            o0.y = acc[mi][ni][1] + bv.y;
            o1.x = acc[mi][ni][2] + bv.x;
            o1.y = acc[mi][ni][3] + bv.y;
            *(float2*)(C + (size_t)row * N + col) = o0;
            *(float2*)(C + (size_t)(row + 8) * N + col) = o1;
        }
    }
}

// ---------------------------------------------------------------------------
// Tensor-core flash attention (tf32 MMA, fp32 softmax), ALiBi + causal.
// CTA: 128 queries x 1 head. 8 warps x 16 query rows. Key tiles of 64.
// ---------------------------------------------------------------------------
#define STR 68   // smem row stride (floats); 68 mod 32 = 4 -> conflict-free frags

__global__ __launch_bounds__(256) void attn_mma(
    const float* __restrict__ q, const float* __restrict__ kv,
    float* __restrict__ y)
{
    extern __shared__ float smf[];
    uint32_t* sQu = (uint32_t*)smf;                 // 128*STR : Q tile, then P
    uint32_t* sKu = sQu + 128 * STR;                // 64*STR  : K [key][d]
    uint32_t* sVu = sKu + 64 * STR;                 // 64*STR  : V [d][key]

    const int tid = threadIdx.x;
    const int wid = tid >> 5, lane = tid & 31;
    const int grp = lane >> 2, qid = lane & 3;
    const int qt = (int)gridDim.x - 1 - (int)blockIdx.x;   // big tiles first
    const int h = blockIdx.y, b = blockIdx.z;
    const int q0 = qt * 128;
    const float slope = (float)(h + 1) * (1.0f / NHEAD);

    // ---- Q load (warp-local rows: tid>>1 gives warp w rows 16w..16w+15) ----
    {
        const int row = tid >> 1;
        const int ch = (tid & 1) * 32;
        const float* src = q + ((size_t)(b * SEQ + q0 + row)) * DMODEL + h * HDIM + ch;
        uint32_t* dst = sQu + row * STR + ch;
#pragma unroll
        for (int u = 0; u < 8; u++) {
            float4 v = *(const float4*)(src + 4 * u);
            dst[4 * u + 0] = f2tf32(v.x); dst[4 * u + 1] = f2tf32(v.y);
            dst[4 * u + 2] = f2tf32(v.z); dst[4 * u + 3] = f2tf32(v.w);
        }
    }
    __syncwarp();

    const int prow = (16 * wid + grp) * STR;
    uint32_t qfr[8][4];
#pragma unroll
    for (int ks = 0; ks < 8; ks++) {
        const int c0 = ks * 8 + qid;
        qfr[ks][0] = sQu[prow + c0];
        qfr[ks][1] = sQu[prow + 8 * STR + c0];
        qfr[ks][2] = sQu[prow + c0 + 4];
        qfr[ks][3] = sQu[prow + 8 * STR + c0 + 4];
    }
    __syncwarp();

    float m_[2] = {-1e30f, -1e30f};
    float l_[2] = {0.0f, 0.0f};
    float oacc[8][4];
#pragma unroll
    for (int ni = 0; ni < 8; ni++)
#pragma unroll
        for (int v = 0; v < 4; v++) oacc[ni][v] = 0.0f;

    const int qg0 = q0 + 16 * wid + grp;   // row for c0/c1; c2/c3 at qg0+8
    const int ktmax = 2 * qt + 1;

    for (int kt = 0; kt <= ktmax; kt++) {
        const int k0 = kt * 64;
        __syncthreads();   // prior tile's frag reads of sK/sV complete

        // ---- load K [key][d] and V [d][key] (tf32-converted) ----
        {
            const int key = tid >> 2, db = (tid & 3) * 16;
            const float* src = kv + ((size_t)(b * SEQ + k0 + key)) * (2 * DMODEL) + h * HDIM + db;
            uint32_t* dst = sKu + key * STR + db;
#pragma unroll
            for (int u = 0; u < 4; u++) {
                float4 v = *(const float4*)(src + 4 * u);
                dst[4 * u + 0] = f2tf32(v.x); dst[4 * u + 1] = f2tf32(v.y);
                dst[4 * u + 2] = f2tf32(v.z); dst[4 * u + 3] = f2tf32(v.w);
            }
            const int vkey = tid & 63, vdb = (tid >> 6) * 16;
            const float* vsrc = kv + ((size_t)(b * SEQ + k0 + vkey)) * (2 * DMODEL)
                                + DMODEL + h * HDIM + vdb;
#pragma unroll
            for (int u = 0; u < 4; u++) {
                float4 v = *(const float4*)(vsrc + 4 * u);
                sVu[(vdb + 4 * u + 0) * STR + vkey] = f2tf32(v.x);
                sVu[(vdb + 4 * u + 1) * STR + vkey] = f2tf32(v.y);
                sVu[(vdb + 4 * u + 2) * STR + vkey] = f2tf32(v.z);
                sVu[(vdb + 4 * u + 3) * STR + vkey] = f2tf32(v.w);
            }
        }
        __syncthreads();

        // ---- S = Q @ K^T ----
        float sacc[8][4];
#pragma unroll
        for (int ni = 0; ni < 8; ni++)
#pragma unroll
            for (int v = 0; v < 4; v++) sacc[ni][v] = 0.0f;

#pragma unroll
        for (int ks = 0; ks < 8; ks++) {
#pragma unroll
            for (int ni = 0; ni < 8; ni++) {
                uint32_t bfr[2];
                const int ba = (ni * 8 + grp) * STR + ks * 8 + qid;
                bfr[0] = sKu[ba];
                bfr[1] = sKu[ba + 4];
                mma_tf32(sacc[ni], qfr[ks], bfr);
            }
        }

        // ---- scale + ALiBi + causal mask (fp32) ----
        const bool needmask = (kt >= 2 * qt);
        float mx0 = -1e30f, mx1 = -1e30f;
#pragma unroll
        for (int ni = 0; ni < 8; ni++) {
            const int key0 = k0 + ni * 8 + 2 * qid;
            const float d0 = (float)(key0 - qg0);
            float v0 = fmaf(sacc[ni][0], 0.125f, slope * d0);
            float v1 = fmaf(sacc[ni][1], 0.125f, slope * (d0 + 1.0f));
            float v2 = fmaf(sacc[ni][2], 0.125f, slope * (d0 - 8.0f));
            float v3 = fmaf(sacc[ni][3], 0.125f, slope * (d0 - 7.0f));
            if (needmask) {
                if (key0     > qg0)     v0 = -1e30f;
                if (key0 + 1 > qg0)     v1 = -1e30f;
                if (key0     > qg0 + 8) v2 = -1e30f;
                if (key0 + 1 > qg0 + 8) v3 = -1e30f;
            }
            sacc[ni][0] = v0; sacc[ni][1] = v1;
            sacc[ni][2] = v2; sacc[ni][3] = v3;
            mx0 = fmaxf(mx0, fmaxf(v0, v1));
            mx1 = fmaxf(mx1, fmaxf(v2, v3));
        }
        mx0 = fmaxf(mx0, __shfl_xor_sync(0xffffffffu, mx0, 1));
        mx0 = fmaxf(mx0, __shfl_xor_sync(0xffffffffu, mx0, 2));
        mx1 = fmaxf(mx1, __shfl_xor_sync(0xffffffffu, mx1, 1));
        mx1 = fmaxf(mx1, __shfl_xor_sync(0xffffffffu, mx1, 2));

        const float mn0 = fmaxf(m_[0], mx0);
        const float mn1 = fmaxf(m_[1], mx1);
        const float sc0 = __expf(m_[0] - mn0);
        const float sc1 = __expf(m_[1] - mn1);
        m_[0] = mn0; m_[1] = mn1;

        float rs0 = 0.0f, rs1 = 0.0f;
#pragma unroll
        for (int ni = 0; ni < 8; ni++) {
            const float p0 = __expf(sacc[ni][0] - mn0);
            const float p1 = __expf(sacc[ni][1] - mn0);
            const float p2 = __expf(sacc[ni][2] - mn1);
            const float p3 = __expf(sacc[ni][3] - mn1);
            rs0 += p0 + p1;
            rs1 += p2 + p3;
            uint2 w0; w0.x = f2tf32(p0); w0.y = f2tf32(p1);
            *(uint2*)&sQu[prow + ni * 8 + 2 * qid] = w0;
            uint2 w1; w1.x = f2tf32(p2); w1.y = f2tf32(p3);
            *(uint2*)&sQu[prow + 8 * STR + ni * 8 + 2 * qid] = w1;
        }
        rs0 += __shfl_xor_sync(0xffffffffu, rs0, 1);
        rs0 += __shfl_xor_sync(0xffffffffu, rs0, 2);
        rs1 += __shfl_xor_sync(0xffffffffu, rs1, 1);
        rs1 += __shfl_xor_sync(0xffffffffu, rs1, 2);
        l_[0] = l_[0] * sc0 + rs0;
        l_[1] = l_[1] * sc1 + rs1;

#pragma unroll
        for (int ni = 0; ni < 8; ni++) {
            oacc[ni][0] *= sc0; oacc[ni][1] *= sc0;
            oacc[ni][2] *= sc1; oacc[ni][3] *= sc1;
        }
        __syncwarp();   // P visible to own warp

        // ---- O += P @ V ----
#pragma unroll
        for (int ks = 0; ks < 8; ks++) {
            uint32_t pa[4];
            const int c0 = ks * 8 + qid;
            pa[0] = sQu[prow + c0];
            pa[1] = sQu[prow + 8 * STR + c0];
            pa[2] = sQu[prow + c0 + 4];
            pa[3] = sQu[prow + 8 * STR + c0 + 4];
#pragma unroll
            for (int ni = 0; ni < 8; ni++) {
                uint32_t bfr[2];
                const int ba = (ni * 8 + grp) * STR + ks * 8 + qid;
                bfr[0] = sVu[ba];
                bfr[1] = sVu[ba + 4];
                mma_tf32(oacc[ni], pa, bfr);
            }
        }
    }

    // ---- epilogue ----
    const float inv0 = 1.0f / l_[0];
    const float inv1 = 1.0f / l_[1];
    float* d0p = y + ((size_t)(b * SEQ + qg0)) * DMODEL + h * HDIM;
    float* d1p = d0p + (size_t)8 * DMODEL;
#pragma unroll
    for (int ni = 0; ni < 8; ni++) {
        const int c = ni * 8 + 2 * qid;
        float2 o0; o0.x = oacc[ni][0] * inv0; o0.y = oacc[ni][1] * inv0;
        *(float2*)(d0p + c) = o0;
        float2 o1; o1.x = oacc[ni][2] * inv1; o1.y = oacc[ni][3] * inv1;
        *(float2*)(d1p + c) = o1;
    }
}

// ---------------------------------------------------------------------------
extern "C" void kernel_launch(void* const* d_in, const int* in_sizes, int n_in,
                              void* d_out, int out_size)
{
    const float* x   = (const float*)d_in[0];
    const float* Wq  = (const float*)d_in[2];
    const float* bq  = (const float*)d_in[3];
    const float* Wkv = (const float*)d_in[4];
    const float* bkv = (const float*)d_in[5];
    const float* Wo  = (const float*)d_in[6];
    const float* bo  = (const float*)d_in[7];
    float* out = (float*)d_out;

    void *pq, *pkv, *py;
    cudaGetSymbolAddress(&pq, g_q);
    cudaGetSymbolAddress(&pkv, g_kv);
    cudaGetSymbolAddress(&py, g_y);
    float* qb  = (float*)pq;
    float* kvb = (float*)pkv;
    float* yb  = (float*)py;

    const int gemm_smem = 2 * 2 * GBUF * 4;   // 73728 B
    cudaFuncSetAttribute(mma_gemm_nt_bias,
                         cudaFuncAttributeMaxDynamicSharedMemorySize, gemm_smem);

    mma_gemm_nt_bias<<<dim3(DMODEL / 128, MTOT / 128), 256, gemm_smem>>>(
        x, Wq, bq, qb, DMODEL, DMODEL);

    mma_gemm_nt_bias<<<dim3(2 * DMODEL / 128, MTOT / 128), 256, gemm_smem>>>(
        x, Wkv, bkv, kvb, 2 * DMODEL, DMODEL);

    const int attn_smem = (128 + 64 + 64) * STR * 4;   // 69632 B
    cudaFuncSetAttribute(attn_mma,
                         cudaFuncAttributeMaxDynamicSharedMemorySize, attn_smem);
    attn_mma<<<dim3(SEQ / 128, NHEAD, BATCH), 256, attn_smem>>>(qb, kvb, yb);

    mma_gemm_nt_bias<<<dim3(DMODEL / 128, MTOT / 128), 256, gemm_smem>>>(
        yb, Wo, bo, out, DMODEL, DMODEL);
}